// round 9
// baseline (speedup 1.0000x reference)
#include <cuda_runtime.h>
#include <cuda_bf16.h>

typedef unsigned int u32;
typedef unsigned long long u64;

#define N_ROWS 2048
#define K_CODES 81920
#define C_DIM 64
#define M_TILE 128
#define N_TILE 128
#define CHUNK 1024
#define TILES (CHUNK / N_TILE)     // 8
#define NCHUNKS (K_CODES / CHUNK)  // 80
#define PITCH 72                   // bf16 elems per smem row (144 B, conflict-free)
#define CAP 2048
#define NSEED 1024

// ---------------- device scratch (no allocation allowed) -------------------
__device__ __nv_bfloat16 g_zbf[N_ROWS * C_DIM];
__device__ __nv_bfloat16 g_ebf[K_CODES * C_DIM];
__device__ float g_enorm[K_CODES];
__device__ float g_znorm[N_ROWS];
__device__ float g_sumabs[N_ROWS];
__device__ u32 g_smin[N_ROWS];     // orderable-uint float
__device__ u32 g_emax;             // bits of max|emb|
__device__ int g_cnt[N_ROWS];
__device__ int g_cand[N_ROWS * CAP];
__device__ double g_rowloss[N_ROWS];

// ---------------- helpers ---------------------------------------------------
__device__ __forceinline__ u32 f2o(float f) {
    u32 b = __float_as_uint(f);
    return (b & 0x80000000u) ? ~b : (b | 0x80000000u);
}
__device__ __forceinline__ float o2f(u32 o) {
    u32 b = (o & 0x80000000u) ? (o ^ 0x80000000u) : ~o;
    return __uint_as_float(b);
}
__device__ __forceinline__ u32 smem_u32(const void* p) {
    u32 a; asm("{ .reg .u64 t; cvta.to.shared.u64 t, %1; cvt.u32.u64 %0, t; }"
               : "=r"(a) : "l"(p));
    return a;
}
__device__ __forceinline__ void cpa16(u32 dst, const void* src) {
    asm volatile("cp.async.cg.shared.global [%0], [%1], 16;" :: "r"(dst), "l"(src));
}
__device__ __forceinline__ void cpa_commit() { asm volatile("cp.async.commit_group;"); }
template <int N> __device__ __forceinline__ void cpa_wait() {
    asm volatile("cp.async.wait_group %0;" :: "n"(N));
}
__device__ __forceinline__ void mma16816(float* d, const u32* a, u32 b0, u32 b1) {
    asm volatile(
        "mma.sync.aligned.m16n8k16.row.col.f32.bf16.bf16.f32 "
        "{%0,%1,%2,%3},{%4,%5,%6,%7},{%8,%9},{%0,%1,%2,%3};"
        : "+f"(d[0]), "+f"(d[1]), "+f"(d[2]), "+f"(d[3])
        : "r"(a[0]), "r"(a[1]), "r"(a[2]), "r"(a[3]), "r"(b0), "r"(b1));
}

// ---------------------------------------------------------------------------
// Prep — R8 VERBATIM (proven-fast configuration).
// ---------------------------------------------------------------------------
__global__ void vq_prep(const float* __restrict__ z, const float* __restrict__ emb) {
    __shared__ float sMax[256];
    int tid = threadIdx.x;
    int t = blockIdx.x * 256 + tid;
    float lmax = 0.f;
    if (t < K_CODES) {
        const float* e = emb + (size_t)t * C_DIM;
        float s = 0.f;
#pragma unroll
        for (int c = 0; c < C_DIM; ++c) {
            float v = e[c];
            s = fmaf(v, v, s);
            lmax = fmaxf(lmax, fabsf(v));
            g_ebf[(size_t)t * C_DIM + c] = __float2bfloat16_rn(v);
        }
        g_enorm[t] = s;
    } else if (t < K_CODES + N_ROWS) {
        int r = t - K_CODES;
        const float* zr = z + (size_t)r * C_DIM;
        float s = 0.f, sa = 0.f;
#pragma unroll
        for (int c = 0; c < C_DIM; ++c) {
            float v = zr[c];
            s = fmaf(v, v, s);
            sa += fabsf(v);
            g_zbf[(size_t)r * C_DIM + c] = __float2bfloat16_rn(v);
        }
        g_znorm[r] = s;
        g_sumabs[r] = sa;
        g_smin[r] = 0xFFFFFFFFu;
        g_cnt[r] = 0;
    }
    sMax[tid] = lmax;
    __syncthreads();
#pragma unroll
    for (int st = 128; st >= 1; st >>= 1) {
        if (tid < st) sMax[tid] = fmaxf(sMax[tid], sMax[tid + st]);
        __syncthreads();
    }
    if (tid == 0 && sMax[0] > 0.f) atomicMax(&g_emax, __float_as_uint(sMax[0]));
}

// ---------------------------------------------------------------------------
// Seed: per-row exact min of s over codes 0..NSEED-1 -> g_smin.
// Replaces GEMM pass 0. thr = seed_min + margin >= true_min + margin, so the
// collection pass still gathers a superset of the required candidate set.
// ---------------------------------------------------------------------------
__global__ void vq_seed(const float* __restrict__ z, const float* __restrict__ emb) {
    __shared__ float sZ[8][C_DIM];
    int tid = threadIdx.x, lane = tid & 31, w = tid >> 5;
    int rowBlk = blockIdx.x * 8;
    for (int i = tid; i < 8 * C_DIM; i += 256)
        sZ[i >> 6][i & 63] = z[(size_t)(rowBlk + (i >> 6)) * C_DIM + (i & 63)];
    __syncthreads();
    int row = rowBlk + w;
    const float* zr = sZ[w];
    float best = __int_as_float(0x7F800000);
#pragma unroll 4
    for (int j = 0; j < NSEED / 32; ++j) {
        int k = lane + 32 * j;
        const float* e = emb + (size_t)k * C_DIM;
        float dot = 0.f;
#pragma unroll
        for (int c = 0; c < C_DIM; ++c) dot = fmaf(zr[c], e[c], dot);
        float s = __fsub_rn(g_enorm[k], __fmul_rn(2.0f, dot));
        best = fminf(best, s);
    }
#pragma unroll
    for (int st = 16; st >= 1; st >>= 1)
        best = fminf(best, __shfl_xor_sync(0xFFFFFFFFu, best, st));
    if (lane == 0) g_smin[row] = f2o(best);
}

// ---------------------------------------------------------------------------
// bf16 HMMA filter — R8 VERBATIM. Launched once with pass=1 (collection);
// thresholds read from g_smin ONCE at kernel start into registers.
// ---------------------------------------------------------------------------
__global__ __launch_bounds__(256, 2) void vq_mma_pass(int pass) {
    extern __shared__ char smem[];
    __nv_bfloat16* sA = (__nv_bfloat16*)smem;               // 128 x PITCH
    const u32 sbase = smem_u32(smem);
    // offsets: A 0..18432, B0 18432, B1 36864, En0 55296, En1 55808, sMin 56320
    float* sMin = (float*)(smem + 56320);

    const int tid = threadIdx.x, lane = tid & 31, wid = tid >> 5;
    const int warp_m = wid >> 1, warp_n = wid & 1;
    const int g = lane >> 2, tq = lane & 3;
    const int rowBase = blockIdx.y * M_TILE;
    const int kChunk = blockIdx.x * CHUNK;

    // group 0: A tile + B tile 0 + En0
#pragma unroll
    for (int j = 0; j < 4; ++j) {
        int idx = tid + 256 * j, r = idx >> 3, sg = idx & 7;
        cpa16(sbase + r * (PITCH * 2) + sg * 16,
              g_zbf + (size_t)(rowBase + r) * C_DIM + sg * 8);
        cpa16(sbase + 18432 + r * (PITCH * 2) + sg * 16,
              g_ebf + (size_t)(kChunk + r) * C_DIM + sg * 8);
    }
    if (tid < 32) cpa16(sbase + 55296 + tid * 16, g_enorm + kChunk + tid * 4);
    cpa_commit();

    float thr[2][2], runmin[2][2];
#pragma unroll
    for (int am = 0; am < 2; ++am)
#pragma unroll
        for (int h = 0; h < 2; ++h) {
            runmin[am][h] = __int_as_float(0x7F800000);
            if (pass) {
                int r = rowBase + warp_m * 32 + am * 16 + g + 8 * h;
                float smin = o2f(g_smin[r]);
                float emax = __uint_as_float(g_emax);
                // 4*errdot + tie-bin + slack (worst-case over-bounds)
                float margin = 4.0f * 0.0082f * emax * g_sumabs[r]
                             + g_znorm[r] * 9.5367431640625e-07f + 2e-6f;
                thr[am][h] = smin + margin;
            } else thr[am][h] = 0.f;
        }

    for (int t = 0; t < TILES; ++t) {
        int buf = t & 1;
        if (t + 1 < TILES) {
            u32 db = sbase + (((t + 1) & 1) ? 36864u : 18432u);
            const __nv_bfloat16* src =
                g_ebf + (size_t)(kChunk + (t + 1) * N_TILE) * C_DIM;
#pragma unroll
            for (int j = 0; j < 4; ++j) {
                int idx = tid + 256 * j, r = idx >> 3, sg = idx & 7;
                cpa16(db + r * (PITCH * 2) + sg * 16, src + (size_t)r * C_DIM + sg * 8);
            }
            if (tid < 32)
                cpa16(sbase + (((t + 1) & 1) ? 55808u : 55296u) + tid * 16,
                      g_enorm + kChunk + (t + 1) * N_TILE + tid * 4);
            cpa_commit();
            cpa_wait<1>();
        } else {
            cpa_wait<0>();
        }
        __syncthreads();

        const __nv_bfloat16* B = (__nv_bfloat16*)(smem + (buf ? 36864 : 18432));
        const float* En = (const float*)(smem + (buf ? 55808 : 55296));

        float d[2][8][4];
#pragma unroll
        for (int am = 0; am < 2; ++am)
#pragma unroll
            for (int bn = 0; bn < 8; ++bn)
#pragma unroll
                for (int e = 0; e < 4; ++e) d[am][bn][e] = 0.f;

#pragma unroll
        for (int ks = 0; ks < 4; ++ks) {
            u32 a[2][4];
#pragma unroll
            for (int am = 0; am < 2; ++am) {
                int r0 = warp_m * 32 + am * 16 + g;
                a[am][0] = *(const u32*)(sA + r0 * PITCH + ks * 16 + tq * 2);
                a[am][1] = *(const u32*)(sA + (r0 + 8) * PITCH + ks * 16 + tq * 2);
                a[am][2] = *(const u32*)(sA + r0 * PITCH + ks * 16 + 8 + tq * 2);
                a[am][3] = *(const u32*)(sA + (r0 + 8) * PITCH + ks * 16 + 8 + tq * 2);
            }
#pragma unroll
            for (int bn = 0; bn < 8; ++bn) {
                int n = warp_n * 64 + bn * 8 + g;
                u32 b0 = *(const u32*)(B + n * PITCH + ks * 16 + tq * 2);
                u32 b1 = *(const u32*)(B + n * PITCH + ks * 16 + 8 + tq * 2);
                mma16816(d[0][bn], a[0], b0, b1);
                mma16816(d[1][bn], a[1], b0, b1);
            }
        }

        // epilogue: s compute, min or collect
#pragma unroll
        for (int am = 0; am < 2; ++am)
#pragma unroll
            for (int bn = 0; bn < 8; ++bn)
#pragma unroll
                for (int e = 0; e < 4; ++e) {
                    int col = warp_n * 64 + bn * 8 + 2 * tq + (e & 1);
                    int h = e >> 1;
                    float s = __fsub_rn(En[col], __fmul_rn(2.0f, d[am][bn][e]));
                    if (!pass) {
                        runmin[am][h] = fminf(runmin[am][h], s);
                    } else if (s <= thr[am][h]) {
                        int row = rowBase + warp_m * 32 + am * 16 + g + 8 * h;
                        int k = kChunk + t * N_TILE + col;
                        int ix = atomicAdd(&g_cnt[row], 1);
                        if (ix < CAP) g_cand[(size_t)row * CAP + ix] = k;
                    }
                }
        __syncthreads();
    }

    if (!pass) {
#pragma unroll
        for (int am = 0; am < 2; ++am)
#pragma unroll
            for (int h = 0; h < 2; ++h) {
                float v = runmin[am][h];
                v = fminf(v, __shfl_xor_sync(0xFFFFFFFFu, v, 1));
                v = fminf(v, __shfl_xor_sync(0xFFFFFFFFu, v, 2));
                if (tq == 0) {
                    int r = warp_m * 32 + am * 16 + g + 8 * h;
                    sMin[r * 2 + warp_n] = v;
                }
            }
        __syncthreads();
        if (tid < M_TILE) {
            float v = fminf(sMin[tid * 2], sMin[tid * 2 + 1]);
            atomicMin(&g_smin[rowBase + tid], f2o(v));
        }
    }
}

// ---------------------------------------------------------------------------
// Rescore exactly (R8 VERBATIM — proven).
// ---------------------------------------------------------------------------
__global__ void vq_rescore_finalize(const float* __restrict__ z,
                                    const float* __restrict__ emb,
                                    float* __restrict__ out, int out_size) {
    __shared__ float sZ[2][C_DIM];
    __shared__ u64 sBest[8];
    __shared__ u64 sFinal[2];
    int tid = threadIdx.x, lane = tid & 31, w = tid >> 5;
    int rowBlk = blockIdx.x * 2;
    if (tid < 2 * C_DIM)
        sZ[tid >> 6][tid & 63] = z[(size_t)(rowBlk + (tid >> 6)) * C_DIM + (tid & 63)];
    __syncthreads();

    int wr = w >> 2, wi = w & 3;
    int row = rowBlk + wr;
    float znorm = g_znorm[row];
    int cnt = g_cnt[row];
    const float* zr = sZ[wr];
    u64 best = 0xFFFFFFFFFFFFFFFFull;

    if (cnt <= CAP) {
        for (int i = wi * 32 + lane; i < cnt; i += 128) {
            int k = g_cand[(size_t)row * CAP + i];
            const float* e = emb + (size_t)k * C_DIM;
            float dot = 0.f;
#pragma unroll
            for (int c = 0; c < C_DIM; ++c) dot = fmaf(zr[c], e[c], dot);
            float d2 = __fadd_rn(__fsub_rn(znorm, __fmul_rn(2.0f, dot)), g_enorm[k]);
            u64 p = ((u64)f2o(d2) << 32) | (u32)k;
            best = p < best ? p : best;
        }
    } else {  // overflow fallback: exact full scan (correctness net)
        for (int k = wi * 32 + lane; k < K_CODES; k += 128) {
            const float* e = emb + (size_t)k * C_DIM;
            float dot = 0.f;
#pragma unroll
            for (int c = 0; c < C_DIM; ++c) dot = fmaf(zr[c], e[c], dot);
            float d2 = __fadd_rn(__fsub_rn(znorm, __fmul_rn(2.0f, dot)), g_enorm[k]);
            u64 p = ((u64)f2o(d2) << 32) | (u32)k;
            best = p < best ? p : best;
        }
    }
#pragma unroll
    for (int st = 16; st >= 1; st >>= 1) {
        u64 o = __shfl_xor_sync(0xFFFFFFFFu, best, st);
        best = o < best ? o : best;
    }
    if (lane == 0) sBest[w] = best;
    __syncthreads();
    if (tid < 2) {
        u64 m = sBest[tid * 4];
#pragma unroll
        for (int q = 1; q < 4; ++q) m = sBest[tid * 4 + q] < m ? sBest[tid * 4 + q] : m;
        sFinal[tid] = m;
    }
    __syncthreads();

    if (wi == 0) {
        u32 idx = (u32)sFinal[wr];
        double part = 0.0;
#pragma unroll
        for (int q = 0; q < 2; ++q) {
            int c = lane + 32 * q;
            float e = emb[(size_t)idx * C_DIM + c];
            float zv = zr[c];
            if ((size_t)row * C_DIM + c < (size_t)out_size)
                out[(size_t)row * C_DIM + c] = __fadd_rn(zv, __fsub_rn(e, zv));
            float s = __fsub_rn(zv, e);
            part += (double)__fmul_rn(s, s);
        }
#pragma unroll
        for (int st = 16; st >= 1; st >>= 1)
            part += __shfl_xor_sync(0xFFFFFFFFu, part, st);
        if (lane == 0) {
            g_rowloss[row] = part;
            if (out_size >= 133122) out[131074 + row] = (float)idx;
        }
    }
}

__global__ void vq_loss(float* __restrict__ out, int out_size) {
    __shared__ double sD[256];
    int tid = threadIdx.x;
    double v[8];
#pragma unroll
    for (int q = 0; q < 8; ++q) v[q] = g_rowloss[tid + 256 * q];
    double s = 0.0;
#pragma unroll
    for (int q = 0; q < 8; ++q) s += v[q];
    sD[tid] = s;
    __syncthreads();
#pragma unroll
    for (int st = 128; st >= 1; st >>= 1) {
        if (tid < st) sD[tid] += sD[tid + st];
        __syncthreads();
    }
    if (tid == 0 && out_size >= 133122) {
        float m = (float)(sD[0] / 131072.0);
        out[131072] = m;
        out[131073] = m;
    }
}

// ---------------------------------------------------------------------------
extern "C" void kernel_launch(void* const* d_in, const int* in_sizes, int n_in,
                              void* d_out, int out_size) {
    const float* z = (const float*)d_in[0];
    const float* emb = (const float*)d_in[1];
    if (n_in >= 2 && in_sizes[0] == K_CODES * C_DIM && in_sizes[1] == N_ROWS * C_DIM) {
        const float* t = z; z = emb; emb = t;
    }
    float* out = (float*)d_out;

    cudaFuncSetAttribute(vq_mma_pass,
                         cudaFuncAttributeMaxDynamicSharedMemorySize, 57344);

    vq_prep<<<(K_CODES + N_ROWS) / 256, 256>>>(z, emb);
    vq_seed<<<N_ROWS / 8, 256>>>(z, emb);
    vq_mma_pass<<<dim3(NCHUNKS, N_ROWS / M_TILE), 256, 57344>>>(1);
    vq_rescore_finalize<<<N_ROWS / 2, 256>>>(z, emb, out, out_size);
    vq_loss<<<1, 256>>>(out, out_size);
}

// round 10
// speedup vs baseline: 18.1965x; 18.1965x over previous
#include <cuda_runtime.h>
#include <cuda_bf16.h>

typedef unsigned int u32;
typedef unsigned long long u64;

#define N_ROWS 2048
#define K_CODES 81920
#define C_DIM 64
#define M_TILE 128
#define N_TILE 128
#define CHUNK 1024
#define TILES (CHUNK / N_TILE)     // 8
#define NCHUNKS (K_CODES / CHUNK)  // 80
#define NCHUNKS_SEED 10            // pass-0 sub-grid: codes 0..10239
#define PITCH 72                   // bf16 elems per smem row (144 B, conflict-free)
#define CAP 2048

// ---------------- device scratch (no allocation allowed) -------------------
__device__ __nv_bfloat16 g_zbf[N_ROWS * C_DIM];
__device__ __nv_bfloat16 g_ebf[K_CODES * C_DIM];
__device__ float g_enorm[K_CODES];
__device__ float g_znorm[N_ROWS];
__device__ float g_sumabs[N_ROWS];
__device__ u32 g_smin[N_ROWS];     // orderable-uint float
__device__ u32 g_emax;             // bits of max|emb|
__device__ int g_cnt[N_ROWS];
__device__ int g_cand[N_ROWS * CAP];
__device__ double g_rowloss[N_ROWS];

// ---------------- helpers ---------------------------------------------------
__device__ __forceinline__ u32 f2o(float f) {
    u32 b = __float_as_uint(f);
    return (b & 0x80000000u) ? ~b : (b | 0x80000000u);
}
__device__ __forceinline__ float o2f(u32 o) {
    u32 b = (o & 0x80000000u) ? (o ^ 0x80000000u) : ~o;
    return __uint_as_float(b);
}
__device__ __forceinline__ u32 smem_u32(const void* p) {
    u32 a; asm("{ .reg .u64 t; cvta.to.shared.u64 t, %1; cvt.u32.u64 %0, t; }"
               : "=r"(a) : "l"(p));
    return a;
}
__device__ __forceinline__ void cpa16(u32 dst, const void* src) {
    asm volatile("cp.async.cg.shared.global [%0], [%1], 16;" :: "r"(dst), "l"(src));
}
__device__ __forceinline__ void cpa_commit() { asm volatile("cp.async.commit_group;"); }
template <int N> __device__ __forceinline__ void cpa_wait() {
    asm volatile("cp.async.wait_group %0;" :: "n"(N));
}
__device__ __forceinline__ void mma16816(float* d, const u32* a, u32 b0, u32 b1) {
    asm volatile(
        "mma.sync.aligned.m16n8k16.row.col.f32.bf16.bf16.f32 "
        "{%0,%1,%2,%3},{%4,%5,%6,%7},{%8,%9},{%0,%1,%2,%3};"
        : "+f"(d[0]), "+f"(d[1]), "+f"(d[2]), "+f"(d[3])
        : "r"(a[0]), "r"(a[1]), "r"(a[2]), "r"(a[3]), "r"(b0), "r"(b1));
}

// ---------------------------------------------------------------------------
// Prep — R8 VERBATIM (proven-fast configuration).
// ---------------------------------------------------------------------------
__global__ void vq_prep(const float* __restrict__ z, const float* __restrict__ emb) {
    __shared__ float sMax[256];
    int tid = threadIdx.x;
    int t = blockIdx.x * 256 + tid;
    float lmax = 0.f;
    if (t < K_CODES) {
        const float* e = emb + (size_t)t * C_DIM;
        float s = 0.f;
#pragma unroll
        for (int c = 0; c < C_DIM; ++c) {
            float v = e[c];
            s = fmaf(v, v, s);
            lmax = fmaxf(lmax, fabsf(v));
            g_ebf[(size_t)t * C_DIM + c] = __float2bfloat16_rn(v);
        }
        g_enorm[t] = s;
    } else if (t < K_CODES + N_ROWS) {
        int r = t - K_CODES;
        const float* zr = z + (size_t)r * C_DIM;
        float s = 0.f, sa = 0.f;
#pragma unroll
        for (int c = 0; c < C_DIM; ++c) {
            float v = zr[c];
            s = fmaf(v, v, s);
            sa += fabsf(v);
            g_zbf[(size_t)r * C_DIM + c] = __float2bfloat16_rn(v);
        }
        g_znorm[r] = s;
        g_sumabs[r] = sa;
        g_smin[r] = 0xFFFFFFFFu;
        g_cnt[r] = 0;
    }
    sMax[tid] = lmax;
    __syncthreads();
#pragma unroll
    for (int st = 128; st >= 1; st >>= 1) {
        if (tid < st) sMax[tid] = fmaxf(sMax[tid], sMax[tid + st]);
        __syncthreads();
    }
    if (tid == 0 && sMax[0] > 0.f) atomicMax(&g_emax, __float_as_uint(sMax[0]));
}

// ---------------------------------------------------------------------------
// bf16 HMMA filter — R8 VERBATIM.
// pass=0 (launched on NCHUNKS_SEED chunks): per-row min of s=enorm-2dot over
//   codes 0..NCHUNKS_SEED*CHUNK-1 -> g_smin. Subset min >= true min, so the
//   collection threshold remains a sound over-bound (superset of candidates).
// pass=1 (full grid): collect s <= smin+margin.
// ---------------------------------------------------------------------------
__global__ __launch_bounds__(256, 2) void vq_mma_pass(int pass) {
    extern __shared__ char smem[];
    __nv_bfloat16* sA = (__nv_bfloat16*)smem;               // 128 x PITCH
    const u32 sbase = smem_u32(smem);
    // offsets: A 0..18432, B0 18432, B1 36864, En0 55296, En1 55808, sMin 56320
    float* sMin = (float*)(smem + 56320);

    const int tid = threadIdx.x, lane = tid & 31, wid = tid >> 5;
    const int warp_m = wid >> 1, warp_n = wid & 1;
    const int g = lane >> 2, tq = lane & 3;
    const int rowBase = blockIdx.y * M_TILE;
    const int kChunk = blockIdx.x * CHUNK;

    // group 0: A tile + B tile 0 + En0
#pragma unroll
    for (int j = 0; j < 4; ++j) {
        int idx = tid + 256 * j, r = idx >> 3, sg = idx & 7;
        cpa16(sbase + r * (PITCH * 2) + sg * 16,
              g_zbf + (size_t)(rowBase + r) * C_DIM + sg * 8);
        cpa16(sbase + 18432 + r * (PITCH * 2) + sg * 16,
              g_ebf + (size_t)(kChunk + r) * C_DIM + sg * 8);
    }
    if (tid < 32) cpa16(sbase + 55296 + tid * 16, g_enorm + kChunk + tid * 4);
    cpa_commit();

    float thr[2][2], runmin[2][2];
#pragma unroll
    for (int am = 0; am < 2; ++am)
#pragma unroll
        for (int h = 0; h < 2; ++h) {
            runmin[am][h] = __int_as_float(0x7F800000);
            if (pass) {
                int r = rowBase + warp_m * 32 + am * 16 + g + 8 * h;
                float smin = o2f(g_smin[r]);
                float emax = __uint_as_float(g_emax);
                // 4*errdot + tie-bin + slack (worst-case over-bounds)
                float margin = 4.0f * 0.0082f * emax * g_sumabs[r]
                             + g_znorm[r] * 9.5367431640625e-07f + 2e-6f;
                thr[am][h] = smin + margin;
            } else thr[am][h] = 0.f;
        }

    for (int t = 0; t < TILES; ++t) {
        int buf = t & 1;
        if (t + 1 < TILES) {
            u32 db = sbase + (((t + 1) & 1) ? 36864u : 18432u);
            const __nv_bfloat16* src =
                g_ebf + (size_t)(kChunk + (t + 1) * N_TILE) * C_DIM;
#pragma unroll
            for (int j = 0; j < 4; ++j) {
                int idx = tid + 256 * j, r = idx >> 3, sg = idx & 7;
                cpa16(db + r * (PITCH * 2) + sg * 16, src + (size_t)r * C_DIM + sg * 8);
            }
            if (tid < 32)
                cpa16(sbase + (((t + 1) & 1) ? 55808u : 55296u) + tid * 16,
                      g_enorm + kChunk + (t + 1) * N_TILE + tid * 4);
            cpa_commit();
            cpa_wait<1>();
        } else {
            cpa_wait<0>();
        }
        __syncthreads();

        const __nv_bfloat16* B = (__nv_bfloat16*)(smem + (buf ? 36864 : 18432));
        const float* En = (const float*)(smem + (buf ? 55808 : 55296));

        float d[2][8][4];
#pragma unroll
        for (int am = 0; am < 2; ++am)
#pragma unroll
            for (int bn = 0; bn < 8; ++bn)
#pragma unroll
                for (int e = 0; e < 4; ++e) d[am][bn][e] = 0.f;

#pragma unroll
        for (int ks = 0; ks < 4; ++ks) {
            u32 a[2][4];
#pragma unroll
            for (int am = 0; am < 2; ++am) {
                int r0 = warp_m * 32 + am * 16 + g;
                a[am][0] = *(const u32*)(sA + r0 * PITCH + ks * 16 + tq * 2);
                a[am][1] = *(const u32*)(sA + (r0 + 8) * PITCH + ks * 16 + tq * 2);
                a[am][2] = *(const u32*)(sA + r0 * PITCH + ks * 16 + 8 + tq * 2);
                a[am][3] = *(const u32*)(sA + (r0 + 8) * PITCH + ks * 16 + 8 + tq * 2);
            }
#pragma unroll
            for (int bn = 0; bn < 8; ++bn) {
                int n = warp_n * 64 + bn * 8 + g;
                u32 b0 = *(const u32*)(B + n * PITCH + ks * 16 + tq * 2);
                u32 b1 = *(const u32*)(B + n * PITCH + ks * 16 + 8 + tq * 2);
                mma16816(d[0][bn], a[0], b0, b1);
                mma16816(d[1][bn], a[1], b0, b1);
            }
        }

        // epilogue: s compute, min or collect
#pragma unroll
        for (int am = 0; am < 2; ++am)
#pragma unroll
            for (int bn = 0; bn < 8; ++bn)
#pragma unroll
                for (int e = 0; e < 4; ++e) {
                    int col = warp_n * 64 + bn * 8 + 2 * tq + (e & 1);
                    int h = e >> 1;
                    float s = __fsub_rn(En[col], __fmul_rn(2.0f, d[am][bn][e]));
                    if (!pass) {
                        runmin[am][h] = fminf(runmin[am][h], s);
                    } else if (s <= thr[am][h]) {
                        int row = rowBase + warp_m * 32 + am * 16 + g + 8 * h;
                        int k = kChunk + t * N_TILE + col;
                        int ix = atomicAdd(&g_cnt[row], 1);
                        if (ix < CAP) g_cand[(size_t)row * CAP + ix] = k;
                    }
                }
        __syncthreads();
    }

    if (!pass) {
#pragma unroll
        for (int am = 0; am < 2; ++am)
#pragma unroll
            for (int h = 0; h < 2; ++h) {
                float v = runmin[am][h];
                v = fminf(v, __shfl_xor_sync(0xFFFFFFFFu, v, 1));
                v = fminf(v, __shfl_xor_sync(0xFFFFFFFFu, v, 2));
                if (tq == 0) {
                    int r = warp_m * 32 + am * 16 + g + 8 * h;
                    sMin[r * 2 + warp_n] = v;
                }
            }
        __syncthreads();
        if (tid < M_TILE) {
            float v = fminf(sMin[tid * 2], sMin[tid * 2 + 1]);
            atomicMin(&g_smin[rowBase + tid], f2o(v));
        }
    }
}

// ---------------------------------------------------------------------------
// Rescore exactly (R8 VERBATIM — proven).
// ---------------------------------------------------------------------------
__global__ void vq_rescore_finalize(const float* __restrict__ z,
                                    const float* __restrict__ emb,
                                    float* __restrict__ out, int out_size) {
    __shared__ float sZ[2][C_DIM];
    __shared__ u64 sBest[8];
    __shared__ u64 sFinal[2];
    int tid = threadIdx.x, lane = tid & 31, w = tid >> 5;
    int rowBlk = blockIdx.x * 2;
    if (tid < 2 * C_DIM)
        sZ[tid >> 6][tid & 63] = z[(size_t)(rowBlk + (tid >> 6)) * C_DIM + (tid & 63)];
    __syncthreads();

    int wr = w >> 2, wi = w & 3;
    int row = rowBlk + wr;
    float znorm = g_znorm[row];
    int cnt = g_cnt[row];
    const float* zr = sZ[wr];
    u64 best = 0xFFFFFFFFFFFFFFFFull;

    if (cnt <= CAP) {
        for (int i = wi * 32 + lane; i < cnt; i += 128) {
            int k = g_cand[(size_t)row * CAP + i];
            const float* e = emb + (size_t)k * C_DIM;
            float dot = 0.f;
#pragma unroll
            for (int c = 0; c < C_DIM; ++c) dot = fmaf(zr[c], e[c], dot);
            float d2 = __fadd_rn(__fsub_rn(znorm, __fmul_rn(2.0f, dot)), g_enorm[k]);
            u64 p = ((u64)f2o(d2) << 32) | (u32)k;
            best = p < best ? p : best;
        }
    } else {  // overflow fallback: exact full scan (correctness net)
        for (int k = wi * 32 + lane; k < K_CODES; k += 128) {
            const float* e = emb + (size_t)k * C_DIM;
            float dot = 0.f;
#pragma unroll
            for (int c = 0; c < C_DIM; ++c) dot = fmaf(zr[c], e[c], dot);
            float d2 = __fadd_rn(__fsub_rn(znorm, __fmul_rn(2.0f, dot)), g_enorm[k]);
            u64 p = ((u64)f2o(d2) << 32) | (u32)k;
            best = p < best ? p : best;
        }
    }
#pragma unroll
    for (int st = 16; st >= 1; st >>= 1) {
        u64 o = __shfl_xor_sync(0xFFFFFFFFu, best, st);
        best = o < best ? o : best;
    }
    if (lane == 0) sBest[w] = best;
    __syncthreads();
    if (tid < 2) {
        u64 m = sBest[tid * 4];
#pragma unroll
        for (int q = 1; q < 4; ++q) m = sBest[tid * 4 + q] < m ? sBest[tid * 4 + q] : m;
        sFinal[tid] = m;
    }
    __syncthreads();

    if (wi == 0) {
        u32 idx = (u32)sFinal[wr];
        double part = 0.0;
#pragma unroll
        for (int q = 0; q < 2; ++q) {
            int c = lane + 32 * q;
            float e = emb[(size_t)idx * C_DIM + c];
            float zv = zr[c];
            if ((size_t)row * C_DIM + c < (size_t)out_size)
                out[(size_t)row * C_DIM + c] = __fadd_rn(zv, __fsub_rn(e, zv));
            float s = __fsub_rn(zv, e);
            part += (double)__fmul_rn(s, s);
        }
#pragma unroll
        for (int st = 16; st >= 1; st >>= 1)
            part += __shfl_xor_sync(0xFFFFFFFFu, part, st);
        if (lane == 0) {
            g_rowloss[row] = part;
            if (out_size >= 133122) out[131074 + row] = (float)idx;
        }
    }
}

__global__ void vq_loss(float* __restrict__ out, int out_size) {
    __shared__ double sD[256];
    int tid = threadIdx.x;
    double v[8];
#pragma unroll
    for (int q = 0; q < 8; ++q) v[q] = g_rowloss[tid + 256 * q];
    double s = 0.0;
#pragma unroll
    for (int q = 0; q < 8; ++q) s += v[q];
    sD[tid] = s;
    __syncthreads();
#pragma unroll
    for (int st = 128; st >= 1; st >>= 1) {
        if (tid < st) sD[tid] += sD[tid + st];
        __syncthreads();
    }
    if (tid == 0 && out_size >= 133122) {
        float m = (float)(sD[0] / 131072.0);
        out[131072] = m;
        out[131073] = m;
    }
}

// ---------------------------------------------------------------------------
extern "C" void kernel_launch(void* const* d_in, const int* in_sizes, int n_in,
                              void* d_out, int out_size) {
    const float* z = (const float*)d_in[0];
    const float* emb = (const float*)d_in[1];
    if (n_in >= 2 && in_sizes[0] == K_CODES * C_DIM && in_sizes[1] == N_ROWS * C_DIM) {
        const float* t = z; z = emb; emb = t;
    }
    float* out = (float*)d_out;

    cudaFuncSetAttribute(vq_mma_pass,
                         cudaFuncAttributeMaxDynamicSharedMemorySize, 57344);

    vq_prep<<<(K_CODES + N_ROWS) / 256, 256>>>(z, emb);
    // Seed pass: pass 0 on a 10-chunk sub-grid (codes 0..10239) — one partial
    // wave (~160 CTAs) instead of the full 1280-CTA pass 0.
    vq_mma_pass<<<dim3(NCHUNKS_SEED, N_ROWS / M_TILE), 256, 57344>>>(0);
    // Collection pass: full grid.
    vq_mma_pass<<<dim3(NCHUNKS, N_ROWS / M_TILE), 256, 57344>>>(1);
    vq_rescore_finalize<<<N_ROWS / 2, 256>>>(z, emb, out, out_size);
    vq_loss<<<1, 256>>>(out, out_size);
}

// round 11
// speedup vs baseline: 21.3969x; 1.1759x over previous
#include <cuda_runtime.h>
#include <cuda_bf16.h>

typedef unsigned int u32;
typedef unsigned long long u64;

#define N_ROWS 2048
#define K_CODES 81920
#define C_DIM 64
#define M_TILE 128
#define N_TILE 128
#define CHUNK 1024
#define TILES (CHUNK / N_TILE)     // 8
#define NCHUNKS (K_CODES / CHUNK)  // 80
#define PITCH 72                   // bf16 elems per smem row (144 B, conflict-free)
#define PITCHB 144
#define CAP 2048

// ---------------- device scratch (no allocation allowed) -------------------
__device__ __nv_bfloat16 g_zbf[N_ROWS * C_DIM];
__device__ __nv_bfloat16 g_ebf[K_CODES * C_DIM];
__device__ float g_enorm[K_CODES];
__device__ float g_znorm[N_ROWS];
__device__ float g_sumabs[N_ROWS];
__device__ u32 g_smin[N_ROWS];     // orderable-uint float
__device__ u32 g_emax;             // bits of max|emb|
__device__ int g_cnt[N_ROWS];
__device__ int g_cand[N_ROWS * CAP];
__device__ double g_rowloss[N_ROWS];

// ---------------- helpers ---------------------------------------------------
__device__ __forceinline__ u32 f2o(float f) {
    u32 b = __float_as_uint(f);
    return (b & 0x80000000u) ? ~b : (b | 0x80000000u);
}
__device__ __forceinline__ float o2f(u32 o) {
    u32 b = (o & 0x80000000u) ? (o ^ 0x80000000u) : ~o;
    return __uint_as_float(b);
}
__device__ __forceinline__ u32 smem_u32(const void* p) {
    u32 a; asm("{ .reg .u64 t; cvta.to.shared.u64 t, %1; cvt.u32.u64 %0, t; }"
               : "=r"(a) : "l"(p));
    return a;
}
__device__ __forceinline__ void cpa16(u32 dst, const void* src) {
    asm volatile("cp.async.cg.shared.global [%0], [%1], 16;" :: "r"(dst), "l"(src));
}
__device__ __forceinline__ void cpa_commit() { asm volatile("cp.async.commit_group;"); }
template <int N> __device__ __forceinline__ void cpa_wait() {
    asm volatile("cp.async.wait_group %0;" :: "n"(N));
}
__device__ __forceinline__ void ldsm4(u32* r, u32 addr) {
    asm volatile("ldmatrix.sync.aligned.m8n8.x4.shared.b16 {%0,%1,%2,%3}, [%4];"
                 : "=r"(r[0]), "=r"(r[1]), "=r"(r[2]), "=r"(r[3]) : "r"(addr));
}
__device__ __forceinline__ void mma16816(float* d, const u32* a, u32 b0, u32 b1) {
    asm volatile(
        "mma.sync.aligned.m16n8k16.row.col.f32.bf16.bf16.f32 "
        "{%0,%1,%2,%3},{%4,%5,%6,%7},{%8,%9},{%0,%1,%2,%3};"
        : "+f"(d[0]), "+f"(d[1]), "+f"(d[2]), "+f"(d[3])
        : "r"(a[0]), "r"(a[1]), "r"(a[2]), "r"(a[3]), "r"(b0), "r"(b1));
}

// ---------------------------------------------------------------------------
// Prep — R8 VERBATIM (proven-fast configuration).
// ---------------------------------------------------------------------------
__global__ void vq_prep(const float* __restrict__ z, const float* __restrict__ emb) {
    __shared__ float sMax[256];
    int tid = threadIdx.x;
    int t = blockIdx.x * 256 + tid;
    float lmax = 0.f;
    if (t < K_CODES) {
        const float* e = emb + (size_t)t * C_DIM;
        float s = 0.f;
#pragma unroll
        for (int c = 0; c < C_DIM; ++c) {
            float v = e[c];
            s = fmaf(v, v, s);
            lmax = fmaxf(lmax, fabsf(v));
            g_ebf[(size_t)t * C_DIM + c] = __float2bfloat16_rn(v);
        }
        g_enorm[t] = s;
    } else if (t < K_CODES + N_ROWS) {
        int r = t - K_CODES;
        const float* zr = z + (size_t)r * C_DIM;
        float s = 0.f, sa = 0.f;
#pragma unroll
        for (int c = 0; c < C_DIM; ++c) {
            float v = zr[c];
            s = fmaf(v, v, s);
            sa += fabsf(v);
            g_zbf[(size_t)r * C_DIM + c] = __float2bfloat16_rn(v);
        }
        g_znorm[r] = s;
        g_sumabs[r] = sa;
        g_smin[r] = 0xFFFFFFFFu;
        g_cnt[r] = 0;
    }
    sMax[tid] = lmax;
    __syncthreads();
#pragma unroll
    for (int st = 128; st >= 1; st >>= 1) {
        if (tid < st) sMax[tid] = fmaxf(sMax[tid], sMax[tid + st]);
        __syncthreads();
    }
    if (tid == 0 && sMax[0] > 0.f) atomicMax(&g_emax, __float_as_uint(sMax[0]));
}

// ---------------------------------------------------------------------------
// Two-pass bf16 HMMA filter — R8 structure; ONLY change: fragment loads via
// ldmatrix.x4 (mapping correctness-proven in R5, which passed rel_err 0.0).
// pass=0: per-row min of s=enorm-2dot. pass=1: collect s <= smin+margin.
// ---------------------------------------------------------------------------
__global__ __launch_bounds__(256, 2) void vq_mma_pass(int pass) {
    extern __shared__ char smem[];
    const u32 sbase = smem_u32(smem);
    // offsets: A 0..18432, B0 18432, B1 36864, En0 55296, En1 55808, sMin 56320
    float* sMin = (float*)(smem + 56320);

    const int tid = threadIdx.x, lane = tid & 31, wid = tid >> 5;
    const int warp_m = wid >> 1, warp_n = wid & 1;
    const int g = lane >> 2, tq = lane & 3;
    const int rowBase = blockIdx.y * M_TILE;
    const int kChunk = blockIdx.x * CHUNK;

    // group 0: A tile + B tile 0 + En0
#pragma unroll
    for (int j = 0; j < 4; ++j) {
        int idx = tid + 256 * j, r = idx >> 3, sg = idx & 7;
        cpa16(sbase + r * PITCHB + sg * 16,
              g_zbf + (size_t)(rowBase + r) * C_DIM + sg * 8);
        cpa16(sbase + 18432 + r * PITCHB + sg * 16,
              g_ebf + (size_t)(kChunk + r) * C_DIM + sg * 8);
    }
    if (tid < 32) cpa16(sbase + 55296 + tid * 16, g_enorm + kChunk + tid * 4);
    cpa_commit();

    float thr[2][2], runmin[2][2];
#pragma unroll
    for (int am = 0; am < 2; ++am)
#pragma unroll
        for (int h = 0; h < 2; ++h) {
            runmin[am][h] = __int_as_float(0x7F800000);
            if (pass) {
                int r = rowBase + warp_m * 32 + am * 16 + g + 8 * h;
                float smin = o2f(g_smin[r]);
                float emax = __uint_as_float(g_emax);
                // 4*errdot + tie-bin + slack (worst-case over-bounds)
                float margin = 4.0f * 0.0082f * emax * g_sumabs[r]
                             + g_znorm[r] * 9.5367431640625e-07f + 2e-6f;
                thr[am][h] = smin + margin;
            } else thr[am][h] = 0.f;
        }

    // ldmatrix lane base addresses (R5-proven mapping)
    u32 aoff[2];
#pragma unroll
    for (int am = 0; am < 2; ++am)
        aoff[am] = sbase + (u32)(warp_m * 32 + am * 16 + (lane & 15)) * PITCHB
                 + ((lane >> 4) & 1) * 16;
    const u32 boffl = (u32)(warp_n * 64 + ((lane >> 4) << 3) + (lane & 7)) * PITCHB
                    + ((lane >> 3) & 1) * 16;

    for (int t = 0; t < TILES; ++t) {
        int buf = t & 1;
        if (t + 1 < TILES) {
            u32 db = sbase + (((t + 1) & 1) ? 36864u : 18432u);
            const __nv_bfloat16* src =
                g_ebf + (size_t)(kChunk + (t + 1) * N_TILE) * C_DIM;
#pragma unroll
            for (int j = 0; j < 4; ++j) {
                int idx = tid + 256 * j, r = idx >> 3, sg = idx & 7;
                cpa16(db + r * PITCHB + sg * 16, src + (size_t)r * C_DIM + sg * 8);
            }
            if (tid < 32)
                cpa16(sbase + (((t + 1) & 1) ? 55808u : 55296u) + tid * 16,
                      g_enorm + kChunk + (t + 1) * N_TILE + tid * 4);
            cpa_commit();
            cpa_wait<1>();
        } else {
            cpa_wait<0>();
        }
        __syncthreads();

        const u32 Bb = sbase + (buf ? 36864u : 18432u);
        const float* En = (const float*)(smem + (buf ? 55808 : 55296));

        float d[2][8][4];
#pragma unroll
        for (int am = 0; am < 2; ++am)
#pragma unroll
            for (int bn = 0; bn < 8; ++bn)
#pragma unroll
                for (int e = 0; e < 4; ++e) d[am][bn][e] = 0.f;

#pragma unroll
        for (int ks = 0; ks < 4; ++ks) {
            u32 aa[2][4];
            ldsm4(aa[0], aoff[0] + ks * 32);
            ldsm4(aa[1], aoff[1] + ks * 32);
#pragma unroll
            for (int bp = 0; bp < 4; ++bp) {
                u32 bb[4];
                ldsm4(bb, Bb + boffl + bp * (16 * PITCHB) + ks * 32);
                mma16816(d[0][2 * bp],     aa[0], bb[0], bb[1]);
                mma16816(d[0][2 * bp + 1], aa[0], bb[2], bb[3]);
                mma16816(d[1][2 * bp],     aa[1], bb[0], bb[1]);
                mma16816(d[1][2 * bp + 1], aa[1], bb[2], bb[3]);
            }
        }

        // epilogue: s compute, min or collect (R8 verbatim)
#pragma unroll
        for (int am = 0; am < 2; ++am)
#pragma unroll
            for (int bn = 0; bn < 8; ++bn)
#pragma unroll
                for (int e = 0; e < 4; ++e) {
                    int col = warp_n * 64 + bn * 8 + 2 * tq + (e & 1);
                    int h = e >> 1;
                    float s = __fsub_rn(En[col], __fmul_rn(2.0f, d[am][bn][e]));
                    if (!pass) {
                        runmin[am][h] = fminf(runmin[am][h], s);
                    } else if (s <= thr[am][h]) {
                        int row = rowBase + warp_m * 32 + am * 16 + g + 8 * h;
                        int k = kChunk + t * N_TILE + col;
                        int ix = atomicAdd(&g_cnt[row], 1);
                        if (ix < CAP) g_cand[(size_t)row * CAP + ix] = k;
                    }
                }
        __syncthreads();
    }

    if (!pass) {
#pragma unroll
        for (int am = 0; am < 2; ++am)
#pragma unroll
            for (int h = 0; h < 2; ++h) {
                float v = runmin[am][h];
                v = fminf(v, __shfl_xor_sync(0xFFFFFFFFu, v, 1));
                v = fminf(v, __shfl_xor_sync(0xFFFFFFFFu, v, 2));
                if (tq == 0) {
                    int r = warp_m * 32 + am * 16 + g + 8 * h;
                    sMin[r * 2 + warp_n] = v;
                }
            }
        __syncthreads();
        if (tid < M_TILE) {
            float v = fminf(sMin[tid * 2], sMin[tid * 2 + 1]);
            atomicMin(&g_smin[rowBase + tid], f2o(v));
        }
    }
}

// ---------------------------------------------------------------------------
// Rescore exactly (R8 VERBATIM — proven).
// ---------------------------------------------------------------------------
__global__ void vq_rescore_finalize(const float* __restrict__ z,
                                    const float* __restrict__ emb,
                                    float* __restrict__ out, int out_size) {
    __shared__ float sZ[2][C_DIM];
    __shared__ u64 sBest[8];
    __shared__ u64 sFinal[2];
    int tid = threadIdx.x, lane = tid & 31, w = tid >> 5;
    int rowBlk = blockIdx.x * 2;
    if (tid < 2 * C_DIM)
        sZ[tid >> 6][tid & 63] = z[(size_t)(rowBlk + (tid >> 6)) * C_DIM + (tid & 63)];
    __syncthreads();

    int wr = w >> 2, wi = w & 3;
    int row = rowBlk + wr;
    float znorm = g_znorm[row];
    int cnt = g_cnt[row];
    const float* zr = sZ[wr];
    u64 best = 0xFFFFFFFFFFFFFFFFull;

    if (cnt <= CAP) {
        for (int i = wi * 32 + lane; i < cnt; i += 128) {
            int k = g_cand[(size_t)row * CAP + i];
            const float* e = emb + (size_t)k * C_DIM;
            float dot = 0.f;
#pragma unroll
            for (int c = 0; c < C_DIM; ++c) dot = fmaf(zr[c], e[c], dot);
            float d2 = __fadd_rn(__fsub_rn(znorm, __fmul_rn(2.0f, dot)), g_enorm[k]);
            u64 p = ((u64)f2o(d2) << 32) | (u32)k;
            best = p < best ? p : best;
        }
    } else {  // overflow fallback: exact full scan (correctness net)
        for (int k = wi * 32 + lane; k < K_CODES; k += 128) {
            const float* e = emb + (size_t)k * C_DIM;
            float dot = 0.f;
#pragma unroll
            for (int c = 0; c < C_DIM; ++c) dot = fmaf(zr[c], e[c], dot);
            float d2 = __fadd_rn(__fsub_rn(znorm, __fmul_rn(2.0f, dot)), g_enorm[k]);
            u64 p = ((u64)f2o(d2) << 32) | (u32)k;
            best = p < best ? p : best;
        }
    }
#pragma unroll
    for (int st = 16; st >= 1; st >>= 1) {
        u64 o = __shfl_xor_sync(0xFFFFFFFFu, best, st);
        best = o < best ? o : best;
    }
    if (lane == 0) sBest[w] = best;
    __syncthreads();
    if (tid < 2) {
        u64 m = sBest[tid * 4];
#pragma unroll
        for (int q = 1; q < 4; ++q) m = sBest[tid * 4 + q] < m ? sBest[tid * 4 + q] : m;
        sFinal[tid] = m;
    }
    __syncthreads();

    if (wi == 0) {
        u32 idx = (u32)sFinal[wr];
        double part = 0.0;
#pragma unroll
        for (int q = 0; q < 2; ++q) {
            int c = lane + 32 * q;
            float e = emb[(size_t)idx * C_DIM + c];
            float zv = zr[c];
            if ((size_t)row * C_DIM + c < (size_t)out_size)
                out[(size_t)row * C_DIM + c] = __fadd_rn(zv, __fsub_rn(e, zv));
            float s = __fsub_rn(zv, e);
            part += (double)__fmul_rn(s, s);
        }
#pragma unroll
        for (int st = 16; st >= 1; st >>= 1)
            part += __shfl_xor_sync(0xFFFFFFFFu, part, st);
        if (lane == 0) {
            g_rowloss[row] = part;
            if (out_size >= 133122) out[131074 + row] = (float)idx;
        }
    }
}

__global__ void vq_loss(float* __restrict__ out, int out_size) {
    __shared__ double sD[256];
    int tid = threadIdx.x;
    double v[8];
#pragma unroll
    for (int q = 0; q < 8; ++q) v[q] = g_rowloss[tid + 256 * q];
    double s = 0.0;
#pragma unroll
    for (int q = 0; q < 8; ++q) s += v[q];
    sD[tid] = s;
    __syncthreads();
#pragma unroll
    for (int st = 128; st >= 1; st >>= 1) {
        if (tid < st) sD[tid] += sD[tid + st];
        __syncthreads();
    }
    if (tid == 0 && out_size >= 133122) {
        float m = (float)(sD[0] / 131072.0);
        out[131072] = m;
        out[131073] = m;
    }
}

// ---------------------------------------------------------------------------
extern "C" void kernel_launch(void* const* d_in, const int* in_sizes, int n_in,
                              void* d_out, int out_size) {
    const float* z = (const float*)d_in[0];
    const float* emb = (const float*)d_in[1];
    if (n_in >= 2 && in_sizes[0] == K_CODES * C_DIM && in_sizes[1] == N_ROWS * C_DIM) {
        const float* t = z; z = emb; emb = t;
    }
    float* out = (float*)d_out;

    cudaFuncSetAttribute(vq_mma_pass,
                         cudaFuncAttributeMaxDynamicSharedMemorySize, 57344);

    vq_prep<<<(K_CODES + N_ROWS) / 256, 256>>>(z, emb);
    vq_mma_pass<<<dim3(NCHUNKS, N_ROWS / M_TILE), 256, 57344>>>(0);
    vq_mma_pass<<<dim3(NCHUNKS, N_ROWS / M_TILE), 256, 57344>>>(1);
    vq_rescore_finalize<<<N_ROWS / 2, 256>>>(z, emb, out, out_size);
    vq_loss<<<1, 256>>>(out, out_size);
}